// round 2
// baseline (speedup 1.0000x reference)
#include <cuda_runtime.h>
#include <math.h>

#define B_  16
#define C_  128
#define T_  16384
#define H_  4
#define D_  32

// ---------------- scratch (static device globals; no runtime alloc) ----------
__device__ float g_eq[B_ * C_ * T_];   // exp(q)          128 MB
__device__ float g_ek[B_ * C_ * T_];   // exp(k)          128 MB
__device__ float g_v [B_ * C_ * T_];   // v raw           128 MB
__device__ float g_op[B_ * C_ * T_];   // pre-GN output   128 MB
__device__ float g_Sq[B_ * C_];        // sum exp(q) per (b, h*32+d)
__device__ float g_Sk[B_ * C_];
__device__ float g_ctx[B_ * H_ * D_ * D_];  // raw k-v contraction
__device__ float g_M[B_ * C_ * C_];         // fused (W_out x ctx) matrix
__device__ float g_stats[B_ * 2];           // GN sum / sumsq

// ---------------- K0: zero accumulators --------------------------------------
__global__ void k_zero()
{
    int i = blockIdx.x * 256 + threadIdx.x;
    if (i < B_ * C_)            { g_Sq[i] = 0.f; g_Sk[i] = 0.f; }
    if (i < B_ * H_ * D_ * D_)  g_ctx[i]  = 0.f;
    if (i < B_ * 2)             g_stats[i] = 0.f;
}

// ---------------- K1: QKV GEMM + softmax-exp epilogue ------------------------
// C[o,t] = sum_c W[o,c] * x[b,c,t].  Block tile 128(o) x 128(t), BK=8,
// 256 threads, 8x8 register tile.  blockIdx.y selects q/k/v o-slab.
__global__ __launch_bounds__(256, 2) void k_qkv(const float* __restrict__ x,
                                                const float* __restrict__ wqkv)
{
    const int b  = blockIdx.z;
    const int ot = blockIdx.y;            // 0=q, 1=k, 2=v
    const int n0 = blockIdx.x * 128;

    const float* A  = wqkv + ot * (128 * 128);   // [128 o][128 c] row-major
    const float* Bm = x + b * (C_ * T_);         // [128 c][16384 t]

    __shared__ float As[8][128];
    __shared__ float Bs[8][128];
    __shared__ float rsum[128];

    const int tid = threadIdx.x;
    const int tx  = tid & 15;
    const int ty  = tid >> 4;

    float acc[8][8];
#pragma unroll
    for (int i = 0; i < 8; i++)
#pragma unroll
        for (int j = 0; j < 8; j++) acc[i][j] = 0.f;

    const int aRow = tid >> 1;
    const int aCol = (tid & 1) * 4;
    const int bRow = tid >> 5;
    const int bCol = (tid & 31) * 4;

    for (int k0 = 0; k0 < 128; k0 += 8) {
        float4 av = *(const float4*)(A + aRow * 128 + k0 + aCol);
        As[aCol + 0][aRow] = av.x;
        As[aCol + 1][aRow] = av.y;
        As[aCol + 2][aRow] = av.z;
        As[aCol + 3][aRow] = av.w;
        *(float4*)&Bs[bRow][bCol] =
            *(const float4*)(Bm + (k0 + bRow) * T_ + n0 + bCol);
        __syncthreads();
#pragma unroll
        for (int k = 0; k < 8; k++) {
            float a[8], bb[8];
            *(float4*)(a)      = *(const float4*)&As[k][ty * 8];
            *(float4*)(a + 4)  = *(const float4*)&As[k][ty * 8 + 4];
            *(float4*)(bb)     = *(const float4*)&Bs[k][tx * 8];
            *(float4*)(bb + 4) = *(const float4*)&Bs[k][tx * 8 + 4];
#pragma unroll
            for (int i = 0; i < 8; i++)
#pragma unroll
                for (int j = 0; j < 8; j++)
                    acc[i][j] = fmaf(a[i], bb[j], acc[i][j]);
        }
        __syncthreads();
    }

    if (ot == 2) {               // v: store raw
        float* dst = g_v + b * (C_ * T_);
#pragma unroll
        for (int i = 0; i < 8; i++) {
            int row = ty * 8 + i;
            float4 v1 = make_float4(acc[i][0], acc[i][1], acc[i][2], acc[i][3]);
            float4 v2 = make_float4(acc[i][4], acc[i][5], acc[i][6], acc[i][7]);
            *(float4*)(dst + row * T_ + n0 + tx * 8)     = v1;
            *(float4*)(dst + row * T_ + n0 + tx * 8 + 4) = v2;
        }
    } else {                     // q/k: store exp, accumulate row-sums
        float* dst = (ot == 0 ? g_eq : g_ek) + b * (C_ * T_);
        float* S   = (ot == 0 ? g_Sq : g_Sk) + b * C_;
        if (tid < 128) rsum[tid] = 0.f;
        __syncthreads();
#pragma unroll
        for (int i = 0; i < 8; i++) {
            int row = ty * 8 + i;
            float e[8];
            float rs = 0.f;
#pragma unroll
            for (int j = 0; j < 8; j++) { e[j] = expf(acc[i][j]); rs += e[j]; }
            float4 v1 = make_float4(e[0], e[1], e[2], e[3]);
            float4 v2 = make_float4(e[4], e[5], e[6], e[7]);
            *(float4*)(dst + row * T_ + n0 + tx * 8)     = v1;
            *(float4*)(dst + row * T_ + n0 + tx * 8 + 4) = v2;
            atomicAdd(&rsum[row], rs);
        }
        __syncthreads();
        if (tid < 128) atomicAdd(&S[tid], rsum[tid]);
    }
}

// ---------------- K2: ctx[b,h,d,e] = sum_n exp(k[d,n]) * v[e,n] --------------
// grid (32 n-splits, 4 h, 16 b); atomically accumulate raw contraction.
__global__ __launch_bounds__(256) void k_ctx()
{
    const int b = blockIdx.z, h = blockIdx.y, sp = blockIdx.x;
    const float* K = g_ek + (b * C_ + h * D_) * T_;
    const float* V = g_v  + (b * C_ + h * D_) * T_;
    __shared__ float ks[32][68];
    __shared__ float vs[32][68];
    const int tid = threadIdx.x;
    const int d   = tid >> 3;
    const int e0  = (tid & 7) * 4;
    float acc[4] = {0.f, 0.f, 0.f, 0.f};
    const int l = tid * 2;
    for (int n0 = sp * 512; n0 < sp * 512 + 512; n0 += 64) {
#pragma unroll
        for (int q = 0; q < 2; q++) {
            int li = l + q;
            int r  = li >> 4;
            int c4 = (li & 15) * 4;
            *(float4*)&ks[r][c4] = *(const float4*)(K + r * T_ + n0 + c4);
            *(float4*)&vs[r][c4] = *(const float4*)(V + r * T_ + n0 + c4);
        }
        __syncthreads();
#pragma unroll
        for (int j = 0; j < 64; j++) {
            float kd = ks[d][j];
            acc[0] = fmaf(kd, vs[e0 + 0][j], acc[0]);
            acc[1] = fmaf(kd, vs[e0 + 1][j], acc[1]);
            acc[2] = fmaf(kd, vs[e0 + 2][j], acc[2]);
            acc[3] = fmaf(kd, vs[e0 + 3][j], acc[3]);
        }
        __syncthreads();
    }
    float* Cp = g_ctx + ((b * H_ + h) * D_ + d) * D_ + e0;
    atomicAdd(Cp + 0, acc[0]);
    atomicAdd(Cp + 1, acc[1]);
    atomicAdd(Cp + 2, acc[2]);
    atomicAdd(Cp + 3, acc[3]);
}

// ---------------- K3: M[b][o][h*32+d] = sum_e W_out[o][h*32+e]*ctxf[h][d][e] -
// ctxf = scale * ctx / (S_k[d] * S_q[d]).   grid = 16 blocks (one per b).
__global__ __launch_bounds__(256) void k_M(const float* __restrict__ w_out)
{
    const int b = blockIdx.x;
    __shared__ float cf[4][32][32];
    const int tid = threadIdx.x;
    const float scale = 0.17677669529663687f;  // 32^-0.5
    for (int i = tid; i < H_ * D_ * D_; i += 256) {
        int h = i >> 10, d = (i >> 5) & 31;
        float cs = g_ctx[b * (H_ * D_ * D_) + i];
        float sk = g_Sk[b * C_ + h * D_ + d];
        float sq = g_Sq[b * C_ + h * D_ + d];
        ((float*)cf)[i] = scale * cs / (sk * sq);
    }
    __syncthreads();
    for (int i = tid; i < C_ * C_; i += 256) {
        int o = i >> 7, hd = i & 127;
        int h = hd >> 5, d = hd & 31;
        const float* wr = w_out + o * C_ + h * D_;
        float s = 0.f;
#pragma unroll
        for (int e = 0; e < 32; e++) s = fmaf(wr[e], cf[h][d][e], s);
        g_M[b * (C_ * C_) + i] = s;
    }
}

// ---------------- K4: out_pre = M[b] @ exp(q) + b_out; GN moments ------------
__global__ __launch_bounds__(256, 2) void k_out(const float* __restrict__ b_out)
{
    const int b  = blockIdx.z;
    const int n0 = blockIdx.x * 128;
    const float* A  = g_M  + b * (C_ * C_);
    const float* Bm = g_eq + b * (C_ * T_);
    __shared__ float As[8][128];
    __shared__ float Bs[8][128];
    const int tid = threadIdx.x;
    const int tx  = tid & 15;
    const int ty  = tid >> 4;

    float acc[8][8];
#pragma unroll
    for (int i = 0; i < 8; i++)
#pragma unroll
        for (int j = 0; j < 8; j++) acc[i][j] = 0.f;

    const int aRow = tid >> 1;
    const int aCol = (tid & 1) * 4;
    const int bRow = tid >> 5;
    const int bCol = (tid & 31) * 4;

    for (int k0 = 0; k0 < 128; k0 += 8) {
        float4 av = *(const float4*)(A + aRow * 128 + k0 + aCol);
        As[aCol + 0][aRow] = av.x;
        As[aCol + 1][aRow] = av.y;
        As[aCol + 2][aRow] = av.z;
        As[aCol + 3][aRow] = av.w;
        *(float4*)&Bs[bRow][bCol] =
            *(const float4*)(Bm + (k0 + bRow) * T_ + n0 + bCol);
        __syncthreads();
#pragma unroll
        for (int k = 0; k < 8; k++) {
            float a[8], bb[8];
            *(float4*)(a)      = *(const float4*)&As[k][ty * 8];
            *(float4*)(a + 4)  = *(const float4*)&As[k][ty * 8 + 4];
            *(float4*)(bb)     = *(const float4*)&Bs[k][tx * 8];
            *(float4*)(bb + 4) = *(const float4*)&Bs[k][tx * 8 + 4];
#pragma unroll
            for (int i = 0; i < 8; i++)
#pragma unroll
                for (int j = 0; j < 8; j++)
                    acc[i][j] = fmaf(a[i], bb[j], acc[i][j]);
        }
        __syncthreads();
    }

    float s1 = 0.f, s2 = 0.f;
    float* dst = g_op + b * (C_ * T_);
#pragma unroll
    for (int i = 0; i < 8; i++) {
        int row  = ty * 8 + i;
        float bo = b_out[row];
        float v[8];
#pragma unroll
        for (int j = 0; j < 8; j++) {
            v[j] = acc[i][j] + bo;
            s1 += v[j];
            s2 = fmaf(v[j], v[j], s2);
        }
        float4 v1 = make_float4(v[0], v[1], v[2], v[3]);
        float4 v2 = make_float4(v[4], v[5], v[6], v[7]);
        *(float4*)(dst + row * T_ + n0 + tx * 8)     = v1;
        *(float4*)(dst + row * T_ + n0 + tx * 8 + 4) = v2;
    }
#pragma unroll
    for (int off = 16; off > 0; off >>= 1) {
        s1 += __shfl_down_sync(0xffffffffu, s1, off);
        s2 += __shfl_down_sync(0xffffffffu, s2, off);
    }
    if ((tid & 31) == 0) {
        atomicAdd(&g_stats[b * 2 + 0], s1);
        atomicAdd(&g_stats[b * 2 + 1], s2);
    }
}

// ---------------- K5: GroupNorm finalize -------------------------------------
__global__ void k_norm(const float* __restrict__ gnw,
                       const float* __restrict__ gnb,
                       float* __restrict__ out)
{
    int i4 = blockIdx.x * 256 + threadIdx.x;
    int e  = i4 * 4;
    int b  = e >> 21;            // C_*T_ = 2^21
    int c  = (e >> 14) & 127;    // T_ = 2^14
    const float inv = 1.0f / (float)(C_ * T_);
    float m    = g_stats[b * 2 + 0] * inv;
    float var  = g_stats[b * 2 + 1] * inv - m * m;
    float rstd = rsqrtf(var + 1e-5f);
    float w    = gnw[c] * rstd;
    float bias = gnb[c] - m * w;
    float4 v = *(const float4*)(g_op + e);
    v.x = v.x * w + bias;
    v.y = v.y * w + bias;
    v.z = v.z * w + bias;
    v.w = v.w * w + bias;
    *(float4*)(out + e) = v;
}

// ---------------- launch ------------------------------------------------------
extern "C" void kernel_launch(void* const* d_in, const int* in_sizes, int n_in,
                              void* d_out, int out_size)
{
    const float* x    = (const float*)d_in[0];
    const float* wqkv = (const float*)d_in[1];
    const float* wout = (const float*)d_in[2];
    const float* bout = (const float*)d_in[3];
    const float* gnw  = (const float*)d_in[4];
    const float* gnb  = (const float*)d_in[5];
    float* out = (float*)d_out;

    k_zero<<<256, 256>>>();
    k_qkv<<<dim3(128, 3, 16), 256>>>(x, wqkv);
    k_ctx<<<dim3(32, 4, 16), 256>>>();
    k_M<<<16, 256>>>(wout);
    k_out<<<dim3(128, 1, 16), 256>>>(bout);
    k_norm<<<32768, 256>>>(gnw, gnb, out);
}

// round 5
// speedup vs baseline: 1.8710x; 1.8710x over previous
#include <cuda_runtime.h>
#include <cstdint>

#define B_ 16
#define C_ 128
#define T_ 16384
#define H_ 4
#define D_ 32
#define CT (C_ * T_)

__device__ float g_eq[B_ * CT];
__device__ float g_ek[B_ * CT];
__device__ float g_v [B_ * CT];
__device__ float g_op[B_ * CT];
__device__ float g_Sq[B_ * C_];
__device__ float g_Sk[B_ * C_];
__device__ float g_ctx[B_ * H_ * D_ * D_];
__device__ float g_M[B_ * C_ * C_];
__device__ float g_stats[B_ * 2];

// tf32 round: cvt.rna.tf32.f32 requires a .b32 destination register
__device__ __forceinline__ float tf32r(float x) {
    uint32_t y;
    asm("cvt.rna.tf32.f32 %0, %1;" : "=r"(y) : "f"(x));
    return __uint_as_float(y);
}
__device__ __forceinline__ void mma_tf32(float* d, const uint32_t* a, const uint32_t* b2) {
    asm volatile("mma.sync.aligned.m16n8k8.row.col.f32.tf32.tf32.f32 "
        "{%0,%1,%2,%3}, {%4,%5,%6,%7}, {%8,%9}, {%0,%1,%2,%3};"
        : "+f"(d[0]), "+f"(d[1]), "+f"(d[2]), "+f"(d[3])
        : "r"(a[0]), "r"(a[1]), "r"(a[2]), "r"(a[3]), "r"(b2[0]), "r"(b2[1]));
}

// ---- shared 128x128 GEMM core: C = A[128x128] * B[128 x Ttile], K chunk 32 ---
// As stride 36, Bs stride 136 (both conflict-free for m16n8k8 fragment reads)
__device__ __forceinline__ void gemm128(const float* __restrict__ Ag,
                                        const float* __restrict__ Bg, int t0,
                                        float acc[2][8][4],
                                        float (*As)[36], float (*Bs)[136]) {
    const int tid = threadIdx.x, lane = tid & 31, wid = tid >> 5;
    const int wm = (wid >> 1) * 32, wn = (wid & 1) * 64;
    float4 bpre[4];
#pragma unroll
    for (int it = 0; it < 4; it++) {
        int idx = tid + it * 256, row = idx >> 5, c4 = idx & 31;
        bpre[it] = *(const float4*)(Bg + (size_t)row * T_ + t0 + c4 * 4);
    }
    for (int kc = 0; kc < 4; kc++) {
        __syncthreads();
#pragma unroll
        for (int it = 0; it < 4; it++) {          // stage A chunk (L2-resident)
            int idx = tid + it * 256, row = idx >> 3, c4 = idx & 7;
            float4 v = *(const float4*)(Ag + row * 128 + kc * 32 + c4 * 4);
            float4 w = make_float4(tf32r(v.x), tf32r(v.y), tf32r(v.z), tf32r(v.w));
            *(float4*)&As[row][c4 * 4] = w;
        }
#pragma unroll
        for (int it = 0; it < 4; it++) {          // stage B from prefetch regs
            int idx = tid + it * 256, row = idx >> 5, c4 = idx & 31;
            float4 v = bpre[it];
            float4 w = make_float4(tf32r(v.x), tf32r(v.y), tf32r(v.z), tf32r(v.w));
            *(float4*)&Bs[row][c4 * 4] = w;
        }
        __syncthreads();
        if (kc < 3) {
#pragma unroll
            for (int it = 0; it < 4; it++) {      // prefetch next B chunk (DRAM)
                int idx = tid + it * 256, row = idx >> 5, c4 = idx & 31;
                bpre[it] = *(const float4*)(Bg + (size_t)((kc + 1) * 32 + row) * T_
                                            + t0 + c4 * 4);
            }
        }
#pragma unroll
        for (int k8 = 0; k8 < 4; k8++) {
            const int k = k8 * 8;
            uint32_t af[2][4], bf[8][2];
#pragma unroll
            for (int mi = 0; mi < 2; mi++) {
                int r = wm + mi * 16 + (lane >> 2);
                af[mi][0] = __float_as_uint(As[r    ][k +     (lane & 3)]);
                af[mi][1] = __float_as_uint(As[r + 8][k +     (lane & 3)]);
                af[mi][2] = __float_as_uint(As[r    ][k + 4 + (lane & 3)]);
                af[mi][3] = __float_as_uint(As[r + 8][k + 4 + (lane & 3)]);
            }
#pragma unroll
            for (int ni = 0; ni < 8; ni++) {
                int n = wn + ni * 8 + (lane >> 2);
                bf[ni][0] = __float_as_uint(Bs[k +     (lane & 3)][n]);
                bf[ni][1] = __float_as_uint(Bs[k + 4 + (lane & 3)][n]);
            }
#pragma unroll
            for (int mi = 0; mi < 2; mi++)
#pragma unroll
                for (int ni = 0; ni < 8; ni++)
                    mma_tf32(acc[mi][ni], af[mi], bf[ni]);
        }
    }
}

// ---------------- K0: zero ---------------------------------------------------
__global__ void k_zero() {
    int i = blockIdx.x * 256 + threadIdx.x;
    if (i < B_ * C_)           { g_Sq[i] = 0.f; g_Sk[i] = 0.f; }
    if (i < B_ * H_ * D_ * D_) g_ctx[i] = 0.f;
    if (i < B_ * 2)            g_stats[i] = 0.f;
}

// ---------------- K1: QKV GEMM (tensor core) + exp epilogue ------------------
__global__ __launch_bounds__(256, 2) void k_qkv(const float* __restrict__ x,
                                                const float* __restrict__ wqkv) {
    __shared__ __align__(16) float As[128][36];
    __shared__ __align__(16) float Bs[32][136];
    __shared__ float rsum[128];
    const int b = blockIdx.z, ot = blockIdx.y, t0 = blockIdx.x * 128;
    const int tid = threadIdx.x, lane = tid & 31, wid = tid >> 5;
    if (tid < 128) rsum[tid] = 0.f;

    float acc[2][8][4];
#pragma unroll
    for (int mi = 0; mi < 2; mi++)
#pragma unroll
        for (int ni = 0; ni < 8; ni++)
#pragma unroll
            for (int r = 0; r < 4; r++) acc[mi][ni][r] = 0.f;

    gemm128(wqkv + ot * 128 * 128, x + (size_t)b * CT, t0, acc, As, Bs);

    const int wm = (wid >> 1) * 32, wn = (wid & 1) * 64;
    float* dst = (ot == 0 ? g_eq : (ot == 1 ? g_ek : g_v)) + (size_t)b * CT;

    if (ot == 2) {
#pragma unroll
        for (int mi = 0; mi < 2; mi++)
#pragma unroll
            for (int half = 0; half < 2; half++) {
                int r = wm + mi * 16 + (lane >> 2) + half * 8;
#pragma unroll
                for (int ni = 0; ni < 8; ni++) {
                    float2 v = make_float2(acc[mi][ni][half * 2],
                                           acc[mi][ni][half * 2 + 1]);
                    *(float2*)(dst + (size_t)r * T_ + t0 + wn + ni * 8
                               + 2 * (lane & 3)) = v;
                }
            }
    } else {
#pragma unroll
        for (int mi = 0; mi < 2; mi++)
#pragma unroll
            for (int half = 0; half < 2; half++) {
                int r = wm + mi * 16 + (lane >> 2) + half * 8;
                float s = 0.f;
#pragma unroll
                for (int ni = 0; ni < 8; ni++) {
                    float e0 = __expf(acc[mi][ni][half * 2]);
                    float e1 = __expf(acc[mi][ni][half * 2 + 1]);
                    s += e0 + e1;
                    *(float2*)(dst + (size_t)r * T_ + t0 + wn + ni * 8
                               + 2 * (lane & 3)) = make_float2(e0, e1);
                }
                s += __shfl_xor_sync(0xffffffffu, s, 1);
                s += __shfl_xor_sync(0xffffffffu, s, 2);
                if ((lane & 3) == 0) atomicAdd(&rsum[r], s);
            }
        __syncthreads();
        float* S = (ot == 0 ? g_Sq : g_Sk) + b * C_;
        if (tid < 128) atomicAdd(&S[tid], rsum[tid]);
    }
}

// ---------------- K2: ctx[b,h,d,e] = sum_n ek[d,n]*v[e,n] --------------------
__global__ __launch_bounds__(256) void k_ctx() {
    const int b = blockIdx.z, h = blockIdx.y, sp = blockIdx.x;
    const float* K = g_ek + (size_t)(b * C_ + h * D_) * T_;
    const float* V = g_v  + (size_t)(b * C_ + h * D_) * T_;
    __shared__ float ks[32][68];
    __shared__ float vs[32][68];
    const int tid = threadIdx.x;
    const int d  = tid >> 3;
    const int e0 = (tid & 7) * 4;
    float a0 = 0, a1 = 0, a2 = 0, a3 = 0;
    const int l = tid * 2;
    for (int n0 = sp * 512; n0 < sp * 512 + 512; n0 += 64) {
#pragma unroll
        for (int q = 0; q < 2; q++) {
            int li = l + q, r = li >> 4, c4 = (li & 15) * 4;
            *(float4*)&ks[r][c4] = *(const float4*)(K + (size_t)r * T_ + n0 + c4);
            *(float4*)&vs[r][c4] = *(const float4*)(V + (size_t)r * T_ + n0 + c4);
        }
        __syncthreads();
#pragma unroll 4
        for (int j = 0; j < 64; j++) {
            float kd = ks[d][j];
            a0 = fmaf(kd, vs[e0 + 0][j], a0);
            a1 = fmaf(kd, vs[e0 + 1][j], a1);
            a2 = fmaf(kd, vs[e0 + 2][j], a2);
            a3 = fmaf(kd, vs[e0 + 3][j], a3);
        }
        __syncthreads();
    }
    float* Cp = g_ctx + ((b * H_ + h) * D_ + d) * D_ + e0;
    atomicAdd(Cp + 0, a0); atomicAdd(Cp + 1, a1);
    atomicAdd(Cp + 2, a2); atomicAdd(Cp + 3, a3);
}

// ---------------- K3: fused M = W_out x (scaled ctx) -------------------------
__global__ __launch_bounds__(256) void k_M(const float* __restrict__ w_out) {
    const int oseg = blockIdx.x, b = blockIdx.y;
    __shared__ float cf[H_ * D_ * D_];
    const int tid = threadIdx.x;
    const float scale = 0.17677669529663687f;  // 32^-0.5
    for (int i = tid; i < H_ * D_ * D_; i += 256) {
        int h = i >> 10, d = (i >> 5) & 31;
        float sk = g_Sk[b * C_ + h * D_ + d], sq = g_Sq[b * C_ + h * D_ + d];
        cf[i] = scale * g_ctx[b * (H_ * D_ * D_) + i] / (sk * sq);
    }
    __syncthreads();
    for (int i = tid; i < 16 * C_; i += 256) {
        int o = oseg * 16 + (i >> 7), hd = i & 127;
        int h = hd >> 5, d = hd & 31;
        const float* wr = w_out + o * C_ + h * D_;
        const float* cr = cf + (h * D_ + d) * D_;
        float s = 0.f;
#pragma unroll
        for (int e = 0; e < 32; e++) s = fmaf(wr[e], cr[e], s);
        g_M[b * (C_ * C_) + o * C_ + hd] = s;
    }
}

// ---------------- K4: out = M @ eq + bias; GN moments (tensor core) ----------
__global__ __launch_bounds__(256, 2) void k_out(const float* __restrict__ b_out) {
    __shared__ __align__(16) float As[128][36];
    __shared__ __align__(16) float Bs[32][136];
    const int b = blockIdx.y, t0 = blockIdx.x * 128;
    const int tid = threadIdx.x, lane = tid & 31, wid = tid >> 5;

    float acc[2][8][4];
#pragma unroll
    for (int mi = 0; mi < 2; mi++)
#pragma unroll
        for (int ni = 0; ni < 8; ni++)
#pragma unroll
            for (int r = 0; r < 4; r++) acc[mi][ni][r] = 0.f;

    gemm128(g_M + b * 128 * 128, g_eq + (size_t)b * CT, t0, acc, As, Bs);

    const int wm = (wid >> 1) * 32, wn = (wid & 1) * 64;
    float* dst = g_op + (size_t)b * CT;
    float s1 = 0.f, s2 = 0.f;
#pragma unroll
    for (int mi = 0; mi < 2; mi++)
#pragma unroll
        for (int half = 0; half < 2; half++) {
            int r = wm + mi * 16 + (lane >> 2) + half * 8;
            float bo = __ldg(&b_out[r]);
#pragma unroll
            for (int ni = 0; ni < 8; ni++) {
                float v0 = acc[mi][ni][half * 2]     + bo;
                float v1 = acc[mi][ni][half * 2 + 1] + bo;
                s1 += v0 + v1;
                s2 = fmaf(v0, v0, s2); s2 = fmaf(v1, v1, s2);
                *(float2*)(dst + (size_t)r * T_ + t0 + wn + ni * 8
                           + 2 * (lane & 3)) = make_float2(v0, v1);
            }
        }
#pragma unroll
    for (int o = 16; o > 0; o >>= 1) {
        s1 += __shfl_down_sync(0xffffffffu, s1, o);
        s2 += __shfl_down_sync(0xffffffffu, s2, o);
    }
    if (lane == 0) {
        atomicAdd(&g_stats[b * 2 + 0], s1);
        atomicAdd(&g_stats[b * 2 + 1], s2);
    }
}

// ---------------- K5: GroupNorm finalize -------------------------------------
__global__ void k_norm(const float* __restrict__ gnw,
                       const float* __restrict__ gnb,
                       float* __restrict__ out) {
    int i4 = blockIdx.x * 256 + threadIdx.x;
    int e  = i4 * 4;
    int b  = e >> 21;
    int c  = (e >> 14) & 127;
    const float inv = 1.0f / (float)CT;
    float m    = g_stats[b * 2 + 0] * inv;
    float var  = g_stats[b * 2 + 1] * inv - m * m;
    float rstd = rsqrtf(var + 1e-5f);
    float w    = gnw[c] * rstd;
    float bias = gnb[c] - m * w;
    float4 v = *(const float4*)(g_op + e);
    v.x = v.x * w + bias; v.y = v.y * w + bias;
    v.z = v.z * w + bias; v.w = v.w * w + bias;
    *(float4*)(out + e) = v;
}

// ---------------- launch ------------------------------------------------------
extern "C" void kernel_launch(void* const* d_in, const int* in_sizes, int n_in,
                              void* d_out, int out_size)
{
    const float* x    = (const float*)d_in[0];
    const float* wqkv = (const float*)d_in[1];
    const float* wout = (const float*)d_in[2];
    const float* bout = (const float*)d_in[3];
    const float* gnw  = (const float*)d_in[4];
    const float* gnb  = (const float*)d_in[5];
    float* out = (float*)d_out;

    k_zero<<<256, 256>>>();
    k_qkv<<<dim3(T_ / 128, 3, B_), 256>>>(x, wqkv);
    k_ctx<<<dim3(32, H_, B_), 256>>>();
    k_M<<<dim3(8, B_), 256>>>(wout);
    k_out<<<dim3(T_ / 128, B_), 256>>>(bout);
    k_norm<<<32768, 256>>>(gnw, gnb, out);
}

// round 6
// speedup vs baseline: 3.3034x; 1.7656x over previous
#include <cuda_runtime.h>
#include <cstdint>

#define B_ 16
#define C_ 128
#define T_ 16384
#define H_ 4
#define D_ 32
#define CT (C_ * T_)

__device__ float g_eq[B_ * CT];
__device__ float g_ek[B_ * CT];
__device__ float g_v [B_ * CT];
__device__ float g_op[B_ * CT];
__device__ float g_Sq[B_ * C_];
__device__ float g_Sk[B_ * C_];
__device__ float g_ctx[B_ * H_ * D_ * D_];
__device__ float g_M[B_ * C_ * C_];
__device__ float g_stats[B_ * 2];

// tf32 round (cvt.rna.tf32.f32 needs .b32 destination)
__device__ __forceinline__ float tf32r(float x) {
    uint32_t y;
    asm("cvt.rna.tf32.f32 %0, %1;" : "=r"(y) : "f"(x));
    return __uint_as_float(y);
}
__device__ __forceinline__ void mma_tf32(float* d, const uint32_t* a, const uint32_t* b2) {
    asm volatile("mma.sync.aligned.m16n8k8.row.col.f32.tf32.tf32.f32 "
        "{%0,%1,%2,%3}, {%4,%5,%6,%7}, {%8,%9}, {%0,%1,%2,%3};"
        : "+f"(d[0]), "+f"(d[1]), "+f"(d[2]), "+f"(d[3])
        : "r"(a[0]), "r"(a[1]), "r"(a[2]), "r"(a[3]), "r"(b2[0]), "r"(b2[1]));
}

// ---- 128x128 GEMM core used by k_out (unchanged from R5, validated) ---------
__device__ __forceinline__ void gemm128(const float* __restrict__ Ag,
                                        const float* __restrict__ Bg, int t0,
                                        float acc[2][8][4],
                                        float (*As)[36], float (*Bs)[136]) {
    const int tid = threadIdx.x, lane = tid & 31, wid = tid >> 5;
    const int wm = (wid >> 1) * 32, wn = (wid & 1) * 64;
    float4 bpre[4];
#pragma unroll
    for (int it = 0; it < 4; it++) {
        int idx = tid + it * 256, row = idx >> 5, c4 = idx & 31;
        bpre[it] = *(const float4*)(Bg + (size_t)row * T_ + t0 + c4 * 4);
    }
    for (int kc = 0; kc < 4; kc++) {
        __syncthreads();
#pragma unroll
        for (int it = 0; it < 4; it++) {
            int idx = tid + it * 256, row = idx >> 3, c4 = idx & 7;
            float4 v = *(const float4*)(Ag + row * 128 + kc * 32 + c4 * 4);
            float4 w = make_float4(tf32r(v.x), tf32r(v.y), tf32r(v.z), tf32r(v.w));
            *(float4*)&As[row][c4 * 4] = w;
        }
#pragma unroll
        for (int it = 0; it < 4; it++) {
            int idx = tid + it * 256, row = idx >> 5, c4 = idx & 31;
            float4 v = bpre[it];
            float4 w = make_float4(tf32r(v.x), tf32r(v.y), tf32r(v.z), tf32r(v.w));
            *(float4*)&Bs[row][c4 * 4] = w;
        }
        __syncthreads();
        if (kc < 3) {
#pragma unroll
            for (int it = 0; it < 4; it++) {
                int idx = tid + it * 256, row = idx >> 5, c4 = idx & 31;
                bpre[it] = *(const float4*)(Bg + (size_t)((kc + 1) * 32 + row) * T_
                                            + t0 + c4 * 4);
            }
        }
#pragma unroll
        for (int k8 = 0; k8 < 4; k8++) {
            const int k = k8 * 8;
            uint32_t af[2][4], bf[8][2];
#pragma unroll
            for (int mi = 0; mi < 2; mi++) {
                int r = wm + mi * 16 + (lane >> 2);
                af[mi][0] = __float_as_uint(As[r    ][k +     (lane & 3)]);
                af[mi][1] = __float_as_uint(As[r + 8][k +     (lane & 3)]);
                af[mi][2] = __float_as_uint(As[r    ][k + 4 + (lane & 3)]);
                af[mi][3] = __float_as_uint(As[r + 8][k + 4 + (lane & 3)]);
            }
#pragma unroll
            for (int ni = 0; ni < 8; ni++) {
                int n = wn + ni * 8 + (lane >> 2);
                bf[ni][0] = __float_as_uint(Bs[k +     (lane & 3)][n]);
                bf[ni][1] = __float_as_uint(Bs[k + 4 + (lane & 3)][n]);
            }
#pragma unroll
            for (int mi = 0; mi < 2; mi++)
#pragma unroll
                for (int ni = 0; ni < 8; ni++)
                    mma_tf32(acc[mi][ni], af[mi], bf[ni]);
        }
    }
}

// ---------------- K0: zero ---------------------------------------------------
__global__ void k_zero() {
    int i = blockIdx.x * 256 + threadIdx.x;
    if (i < B_ * C_)           { g_Sq[i] = 0.f; g_Sk[i] = 0.f; }
    if (i < B_ * H_ * D_ * D_) g_ctx[i] = 0.f;
    if (i < B_ * 2)            g_stats[i] = 0.f;
}

// ---------------- K1: fused QKV GEMM — x tile resident, 3 slabs --------------
#define QKV_SMEM ((128 * 136 + 128 * 36 + 128) * 4)

__global__ __launch_bounds__(256, 2) void k_qkv(const float* __restrict__ x,
                                                const float* __restrict__ wqkv) {
    extern __shared__ float dsm[];
    float (*Bs)[136] = (float(*)[136])dsm;              // x tile [k=128][t=128]
    float (*As)[36]  = (float(*)[36])(dsm + 128 * 136); // W chunk [o=128][k=32]
    float* rsum      = dsm + 128 * 136 + 128 * 36;
    const int b = blockIdx.y, t0 = blockIdx.x * 128;
    const int tid = threadIdx.x, lane = tid & 31, wid = tid >> 5;
    const int wm = (wid >> 1) * 32, wn = (wid & 1) * 64;

    const float* xb = x + (size_t)b * CT;
#pragma unroll
    for (int it = 0; it < 16; it++) {                   // stage full x tile once
        int idx = tid + it * 256, row = idx >> 5, c4 = (idx & 31) * 4;
        float4 v = *(const float4*)(xb + (size_t)row * T_ + t0 + c4);
        float4 w = make_float4(tf32r(v.x), tf32r(v.y), tf32r(v.z), tf32r(v.w));
        *(float4*)&Bs[row][c4] = w;
    }

    for (int ot = 0; ot < 3; ot++) {
        float acc[2][8][4];
#pragma unroll
        for (int mi = 0; mi < 2; mi++)
#pragma unroll
            for (int ni = 0; ni < 8; ni++)
#pragma unroll
                for (int r = 0; r < 4; r++) acc[mi][ni][r] = 0.f;

        for (int kc = 0; kc < 4; kc++) {
            __syncthreads();
#pragma unroll
            for (int it = 0; it < 4; it++) {            // stage W chunk (L2-hot)
                int idx = tid + it * 256, row = idx >> 3, c4 = (idx & 7) * 4;
                float4 v = *(const float4*)(wqkv + (size_t)(ot * 128 + row) * 128
                                            + kc * 32 + c4);
                float4 w = make_float4(tf32r(v.x), tf32r(v.y), tf32r(v.z), tf32r(v.w));
                *(float4*)&As[row][c4] = w;
            }
            __syncthreads();
#pragma unroll
            for (int k8 = 0; k8 < 4; k8++) {
                const int k = k8 * 8;
                uint32_t af[2][4], bf[8][2];
#pragma unroll
                for (int mi = 0; mi < 2; mi++) {
                    int r = wm + mi * 16 + (lane >> 2);
                    af[mi][0] = __float_as_uint(As[r    ][k +     (lane & 3)]);
                    af[mi][1] = __float_as_uint(As[r + 8][k +     (lane & 3)]);
                    af[mi][2] = __float_as_uint(As[r    ][k + 4 + (lane & 3)]);
                    af[mi][3] = __float_as_uint(As[r + 8][k + 4 + (lane & 3)]);
                }
#pragma unroll
                for (int ni = 0; ni < 8; ni++) {
                    int n = wn + ni * 8 + (lane >> 2);
                    bf[ni][0] = __float_as_uint(Bs[kc * 32 + k +     (lane & 3)][n]);
                    bf[ni][1] = __float_as_uint(Bs[kc * 32 + k + 4 + (lane & 3)][n]);
                }
#pragma unroll
                for (int mi = 0; mi < 2; mi++)
#pragma unroll
                    for (int ni = 0; ni < 8; ni++)
                        mma_tf32(acc[mi][ni], af[mi], bf[ni]);
            }
        }

        float* dst = (ot == 0 ? g_eq : (ot == 1 ? g_ek : g_v)) + (size_t)b * CT;
        if (ot == 2) {
#pragma unroll
            for (int mi = 0; mi < 2; mi++)
#pragma unroll
                for (int half = 0; half < 2; half++) {
                    int r = wm + mi * 16 + (lane >> 2) + half * 8;
#pragma unroll
                    for (int ni = 0; ni < 8; ni++)
                        *(float2*)(dst + (size_t)r * T_ + t0 + wn + ni * 8
                                   + 2 * (lane & 3)) =
                            make_float2(acc[mi][ni][half * 2],
                                        acc[mi][ni][half * 2 + 1]);
                }
        } else {
            __syncthreads();
            if (tid < 128) rsum[tid] = 0.f;
            __syncthreads();
#pragma unroll
            for (int mi = 0; mi < 2; mi++)
#pragma unroll
                for (int half = 0; half < 2; half++) {
                    int r = wm + mi * 16 + (lane >> 2) + half * 8;
                    float s = 0.f;
#pragma unroll
                    for (int ni = 0; ni < 8; ni++) {
                        float e0 = __expf(acc[mi][ni][half * 2]);
                        float e1 = __expf(acc[mi][ni][half * 2 + 1]);
                        s += e0 + e1;
                        *(float2*)(dst + (size_t)r * T_ + t0 + wn + ni * 8
                                   + 2 * (lane & 3)) = make_float2(e0, e1);
                    }
                    s += __shfl_xor_sync(0xffffffffu, s, 1);
                    s += __shfl_xor_sync(0xffffffffu, s, 2);
                    if ((lane & 3) == 0) atomicAdd(&rsum[r], s);
                }
            __syncthreads();
            float* S = (ot == 0 ? g_Sq : g_Sk) + b * C_;
            if (tid < 128) atomicAdd(&S[tid], rsum[tid]);
        }
    }
}

// ---------------- K2: ctx via tensor cores -----------------------------------
// ctx[d,e] = sum_t ek[d,t] * v[e,t]  -> mma row.col, A=ek[d][t], B=v[e][t]
__global__ __launch_bounds__(256) void k_ctx() {
    const int b = blockIdx.z, h = blockIdx.y, sp = blockIdx.x;
    const float* K = g_ek + (size_t)(b * C_ + h * D_) * T_;
    const float* V = g_v  + (size_t)(b * C_ + h * D_) * T_;
    __shared__ float ks[32][68];
    __shared__ float vs[32][68];
    __shared__ float cacc[D_ * D_];
    const int tid = threadIdx.x, lane = tid & 31, wid = tid >> 5;
    const int kb = wid * 8;                 // this warp's K-slice within chunk

    for (int i = tid; i < D_ * D_; i += 256) cacc[i] = 0.f;

    float acc[2][4][4];
#pragma unroll
    for (int mi = 0; mi < 2; mi++)
#pragma unroll
        for (int ni = 0; ni < 4; ni++)
#pragma unroll
            for (int r = 0; r < 4; r++) acc[mi][ni][r] = 0.f;

    const int l2 = tid * 2;
    for (int n0 = sp * 512; n0 < sp * 512 + 512; n0 += 64) {
#pragma unroll
        for (int q = 0; q < 2; q++) {
            int li = l2 + q, r = li >> 4, c4 = (li & 15) * 4;
            float4 kv = *(const float4*)(K + (size_t)r * T_ + n0 + c4);
            float4 vv = *(const float4*)(V + (size_t)r * T_ + n0 + c4);
            *(float4*)&ks[r][c4] = make_float4(tf32r(kv.x), tf32r(kv.y),
                                               tf32r(kv.z), tf32r(kv.w));
            *(float4*)&vs[r][c4] = make_float4(tf32r(vv.x), tf32r(vv.y),
                                               tf32r(vv.z), tf32r(vv.w));
        }
        __syncthreads();
        uint32_t af[2][4], bf[4][2];
#pragma unroll
        for (int mi = 0; mi < 2; mi++) {
            int r = mi * 16 + (lane >> 2);
            af[mi][0] = __float_as_uint(ks[r    ][kb +     (lane & 3)]);
            af[mi][1] = __float_as_uint(ks[r + 8][kb +     (lane & 3)]);
            af[mi][2] = __float_as_uint(ks[r    ][kb + 4 + (lane & 3)]);
            af[mi][3] = __float_as_uint(ks[r + 8][kb + 4 + (lane & 3)]);
        }
#pragma unroll
        for (int ni = 0; ni < 4; ni++) {
            int n = ni * 8 + (lane >> 2);
            bf[ni][0] = __float_as_uint(vs[n][kb +     (lane & 3)]);
            bf[ni][1] = __float_as_uint(vs[n][kb + 4 + (lane & 3)]);
        }
#pragma unroll
        for (int mi = 0; mi < 2; mi++)
#pragma unroll
            for (int ni = 0; ni < 4; ni++)
                mma_tf32(acc[mi][ni], af[mi], bf[ni]);
        __syncthreads();
    }

    // block reduce: shared atomics, then one global atomic pass
#pragma unroll
    for (int mi = 0; mi < 2; mi++)
#pragma unroll
        for (int ni = 0; ni < 4; ni++)
#pragma unroll
            for (int r = 0; r < 4; r++) {
                int d = mi * 16 + (lane >> 2) + (r >> 1) * 8;
                int e = ni * 8 + (lane & 3) * 2 + (r & 1);
                atomicAdd(&cacc[d * D_ + e], acc[mi][ni][r]);
            }
    __syncthreads();
    float* Cp = g_ctx + (size_t)(b * H_ + h) * (D_ * D_);
    for (int i = tid; i < D_ * D_; i += 256) atomicAdd(&Cp[i], cacc[i]);
}

// ---------------- K3: fused M = W_out x (scaled ctx) -------------------------
__global__ __launch_bounds__(256) void k_M(const float* __restrict__ w_out) {
    const int oseg = blockIdx.x, b = blockIdx.y;
    __shared__ float cf[H_ * D_ * D_];
    const int tid = threadIdx.x;
    const float scale = 0.17677669529663687f;  // 32^-0.5
    for (int i = tid; i < H_ * D_ * D_; i += 256) {
        int h = i >> 10, d = (i >> 5) & 31;
        float sk = g_Sk[b * C_ + h * D_ + d], sq = g_Sq[b * C_ + h * D_ + d];
        cf[i] = scale * g_ctx[b * (H_ * D_ * D_) + i] / (sk * sq);
    }
    __syncthreads();
    for (int i = tid; i < 16 * C_; i += 256) {
        int o = oseg * 16 + (i >> 7), hd = i & 127;
        int h = hd >> 5, d = hd & 31;
        const float* wr = w_out + o * C_ + h * D_;
        const float* cr = cf + (h * D_ + d) * D_;
        float s = 0.f;
#pragma unroll
        for (int e = 0; e < 32; e++) s = fmaf(wr[e], cr[e], s);
        g_M[b * (C_ * C_) + o * C_ + hd] = s;
    }
}

// ---------------- K4: out = M @ eq + bias; GN moments ------------------------
__global__ __launch_bounds__(256, 2) void k_out(const float* __restrict__ b_out) {
    __shared__ __align__(16) float As[128][36];
    __shared__ __align__(16) float Bs[32][136];
    const int b = blockIdx.y, t0 = blockIdx.x * 128;
    const int tid = threadIdx.x, lane = tid & 31, wid = tid >> 5;

    float acc[2][8][4];
#pragma unroll
    for (int mi = 0; mi < 2; mi++)
#pragma unroll
        for (int ni = 0; ni < 8; ni++)
#pragma unroll
            for (int r = 0; r < 4; r++) acc[mi][ni][r] = 0.f;

    gemm128(g_M + b * 128 * 128, g_eq + (size_t)b * CT, t0, acc, As, Bs);

    const int wm = (wid >> 1) * 32, wn = (wid & 1) * 64;
    float* dst = g_op + (size_t)b * CT;
    float s1 = 0.f, s2 = 0.f;
#pragma unroll
    for (int mi = 0; mi < 2; mi++)
#pragma unroll
        for (int half = 0; half < 2; half++) {
            int r = wm + mi * 16 + (lane >> 2) + half * 8;
            float bo = __ldg(&b_out[r]);
#pragma unroll
            for (int ni = 0; ni < 8; ni++) {
                float v0 = acc[mi][ni][half * 2]     + bo;
                float v1 = acc[mi][ni][half * 2 + 1] + bo;
                s1 += v0 + v1;
                s2 = fmaf(v0, v0, s2); s2 = fmaf(v1, v1, s2);
                *(float2*)(dst + (size_t)r * T_ + t0 + wn + ni * 8
                           + 2 * (lane & 3)) = make_float2(v0, v1);
            }
        }
#pragma unroll
    for (int o = 16; o > 0; o >>= 1) {
        s1 += __shfl_down_sync(0xffffffffu, s1, o);
        s2 += __shfl_down_sync(0xffffffffu, s2, o);
    }
    if (lane == 0) {
        atomicAdd(&g_stats[b * 2 + 0], s1);
        atomicAdd(&g_stats[b * 2 + 1], s2);
    }
}

// ---------------- K5: GroupNorm finalize -------------------------------------
__global__ void k_norm(const float* __restrict__ gnw,
                       const float* __restrict__ gnb,
                       float* __restrict__ out) {
    int i4 = blockIdx.x * 256 + threadIdx.x;
    int e  = i4 * 4;
    int b  = e >> 21;
    int c  = (e >> 14) & 127;
    const float inv = 1.0f / (float)CT;
    float m    = g_stats[b * 2 + 0] * inv;
    float var  = g_stats[b * 2 + 1] * inv - m * m;
    float rstd = rsqrtf(var + 1e-5f);
    float w    = gnw[c] * rstd;
    float bias = gnb[c] - m * w;
    float4 v = *(const float4*)(g_op + e);
    v.x = v.x * w + bias; v.y = v.y * w + bias;
    v.z = v.z * w + bias; v.w = v.w * w + bias;
    *(float4*)(out + e) = v;
}

// ---------------- launch ------------------------------------------------------
extern "C" void kernel_launch(void* const* d_in, const int* in_sizes, int n_in,
                              void* d_out, int out_size)
{
    const float* x    = (const float*)d_in[0];
    const float* wqkv = (const float*)d_in[1];
    const float* wout = (const float*)d_in[2];
    const float* bout = (const float*)d_in[3];
    const float* gnw  = (const float*)d_in[4];
    const float* gnb  = (const float*)d_in[5];
    float* out = (float*)d_out;

    cudaFuncSetAttribute(k_qkv, cudaFuncAttributeMaxDynamicSharedMemorySize, QKV_SMEM);

    k_zero<<<256, 256>>>();
    k_qkv<<<dim3(T_ / 128, B_), 256, QKV_SMEM>>>(x, wqkv);
    k_ctx<<<dim3(32, H_, B_), 256>>>();
    k_M<<<dim3(8, B_), 256>>>(wout);
    k_out<<<dim3(T_ / 128, B_), 256>>>(bout);
    k_norm<<<32768, 256>>>(gnw, gnb, out);
}